// round 14
// baseline (speedup 1.0000x reference)
#include <cuda_runtime.h>
#include <cstdint>

// ---------------------------------------------------------------------------
// PrunedGroupSum: y[b,g] = (sum over contiguous column group g of x[b,:]) / 20
//   x:           [B, D] float32   (B=1024, D=262144 -> 1 GiB, streaming)
//   group_sizes: [K]    int32     (K=1000, sums to D)
//   out:         [B, K] float32
//
// R14: persistent CTAs + ticket scheduler + one-tile-ahead L2 prefetch.
// Compute body = R12 verbatim (block tile = (group, 32 rows), warp = 8-row
// slice, unroll-2 -> 16 independent LDG.128). Each block prefetches tile
// t+1's 32 row ranges (cp.async.bulk.prefetch.L2, one per row) while doing
// the demand loads of tile t -> prefetch distance ~= one tile (~4us), so
// demand hits L2 instead of loaded DRAM. Tickets keep g-fastest order
// (concurrent-block locality) with dynamic balancing; output deterministic.
// ---------------------------------------------------------------------------

#define MAX_K 4096
#define ROWS_PER_WARP 8
#define ROWS_PER_BLOCK 32

__device__ int g_offsets[MAX_K + 1];
__device__ int g_ticket;

// Single-warp scan (also resets the ticket counter each replay).
__global__ void pgs_scan_warp_kernel(const int* __restrict__ gs, int K) {
    int lane = threadIdx.x;          // 32 threads
    if (lane == 0) g_ticket = 0;
    int base = lane * 32;

    int v[32];
#pragma unroll
    for (int i = 0; i < 32; i += 4) {
        int idx = base + i;
        int4 t = make_int4(0, 0, 0, 0);
        if (idx + 3 < K) {
            t = *reinterpret_cast<const int4*>(gs + idx);
        } else {
            if (idx     < K) t.x = gs[idx];
            if (idx + 1 < K) t.y = gs[idx + 1];
            if (idx + 2 < K) t.z = gs[idx + 2];
            if (idx + 3 < K) t.w = gs[idx + 3];
        }
        v[i] = t.x; v[i + 1] = t.y; v[i + 2] = t.z; v[i + 3] = t.w;
    }

    int total = 0;
#pragma unroll
    for (int i = 0; i < 32; i++) total += v[i];

    int run = total;
#pragma unroll
    for (int o = 1; o < 32; o <<= 1) {
        int n = __shfl_up_sync(0xffffffffu, run, o);
        if (lane >= o) run += n;
    }
    int lane_base = run - total;

    if (lane == 0) g_offsets[0] = 0;
    int acc = lane_base;
#pragma unroll
    for (int i = 0; i < 32; i++) {
        acc += v[i];
        int idx = base + i;
        if (idx < K) g_offsets[idx + 1] = acc;
    }
}

__device__ __forceinline__ float hsum4(float4 v) {
    return (v.x + v.y) + (v.z + v.w);
}

__global__ __launch_bounds__(128, 5) void pgs_persist_kernel(
    const float* __restrict__ x,
    float* __restrict__ out,
    int D, int K, int B, int total_tiles)
{
    __shared__ int s_next[2];

    int tid  = threadIdx.x;
    int warp = tid >> 5;
    int lane = tid & 31;
    const size_t SD = (size_t)D;
    const float inv_tau = 1.0f / 20.0f;

    if (tid == 0) s_next[0] = atomicAdd(&g_ticket, 1);
    __syncthreads();
    int t_cur = s_next[0];
    int par = 0;

    while (t_cur < total_tiles) {
        // grab the next tile and prefetch it while we process the current one
        if (tid == 0) s_next[par ^ 1] = atomicAdd(&g_ticket, 1);
        __syncthreads();
        int t_nxt = s_next[par ^ 1];
        par ^= 1;

        if (t_nxt < total_tiles) {
            int nband = t_nxt / K;
            int ng    = t_nxt - nband * K;
            int ns = g_offsets[ng];
            int ne = g_offsets[ng + 1];
            int ns16 = ns & ~3;
            int ne16 = (ne + 3) & ~3;
            uint32_t pbytes = (uint32_t)(ne16 - ns16) * 4u;
            int nrow = nband * ROWS_PER_BLOCK + warp * ROWS_PER_WARP + lane;
            if (lane < ROWS_PER_WARP && nrow < B && pbytes > 0) {
                const float* psrc = x + (size_t)nrow * SD + ns16;
                asm volatile("cp.async.bulk.prefetch.L2.global [%0], %1;"
                             :: "l"(psrc), "r"(pbytes) : "memory");
            }
        }

        // ---- process current tile (R12 body) ----
        int band = t_cur / K;
        int g    = t_cur - band * K;
        int row0 = band * ROWS_PER_BLOCK + warp * ROWS_PER_WARP;
        int nrows = B - row0;
        if (nrows > ROWS_PER_WARP) nrows = ROWS_PER_WARP;

        if (nrows > 0) {
            int s = g_offsets[g];
            int e = g_offsets[g + 1];
            const float* p = x + (size_t)row0 * SD;

            float acc[ROWS_PER_WARP];
#pragma unroll
            for (int r = 0; r < ROWS_PER_WARP; r++) acc[r] = 0.0f;

            int s4 = (s + 3) & ~3;
            int e4 = e & ~3;

            if (nrows == ROWS_PER_WARP) {
                if (s4 >= e4) {
                    for (int c = s + lane; c < e; c += 32) {
#pragma unroll
                        for (int r = 0; r < ROWS_PER_WARP; r++)
                            acc[r] += __ldcs(p + (size_t)r * SD + c);
                    }
                } else {
                    {
                        int c = s + lane;
                        if (c < s4) {
#pragma unroll
                            for (int r = 0; r < ROWS_PER_WARP; r++)
                                acc[r] += __ldcs(p + (size_t)r * SD + c);
                        }
                    }
                    int c4 = s4 + lane * 4;
                    for (; c4 + 128 < e4; c4 += 256) {
                        float4 v[ROWS_PER_WARP];
                        float4 w[ROWS_PER_WARP];
#pragma unroll
                        for (int r = 0; r < ROWS_PER_WARP; r++)
                            v[r] = __ldcs(reinterpret_cast<const float4*>(p + (size_t)r * SD + c4));
#pragma unroll
                        for (int r = 0; r < ROWS_PER_WARP; r++)
                            w[r] = __ldcs(reinterpret_cast<const float4*>(p + (size_t)r * SD + c4 + 128));
#pragma unroll
                        for (int r = 0; r < ROWS_PER_WARP; r++)
                            acc[r] += hsum4(v[r]) + hsum4(w[r]);
                    }
                    if (c4 < e4) {
                        float4 v[ROWS_PER_WARP];
#pragma unroll
                        for (int r = 0; r < ROWS_PER_WARP; r++)
                            v[r] = __ldcs(reinterpret_cast<const float4*>(p + (size_t)r * SD + c4));
#pragma unroll
                        for (int r = 0; r < ROWS_PER_WARP; r++)
                            acc[r] += hsum4(v[r]);
                    }
                    {
                        int c = e4 + lane;
                        if (c < e) {
#pragma unroll
                            for (int r = 0; r < ROWS_PER_WARP; r++)
                                acc[r] += __ldcs(p + (size_t)r * SD + c);
                        }
                    }
                }
            } else {
                for (int r = 0; r < nrows; r++) {
                    const float* pr = p + (size_t)r * SD;
                    float a = 0.f;
                    for (int c = s + lane; c < e; c += 32) a += __ldcs(pr + c);
                    acc[r] = a;
                }
            }

#pragma unroll
            for (int r = 0; r < ROWS_PER_WARP; r++) {
#pragma unroll
                for (int o = 16; o > 0; o >>= 1)
                    acc[r] += __shfl_xor_sync(0xffffffffu, acc[r], o);
            }

            if (lane == 0) {
                size_t ob = (size_t)row0 * (size_t)K + g;
#pragma unroll
                for (int r = 0; r < ROWS_PER_WARP; r++)
                    if (r < nrows) out[ob + (size_t)r * (size_t)K] = acc[r] * inv_tau;
            }
        }

        t_cur = t_nxt;
    }
}

extern "C" void kernel_launch(void* const* d_in, const int* in_sizes, int n_in,
                              void* d_out, int out_size) {
    const float* x  = (const float*)d_in[0];
    const int*   gs = (const int*)d_in[1];

    int K = in_sizes[1];
    int B = out_size / K;
    int D = in_sizes[0] / B;

    float* out = (float*)d_out;

    pgs_scan_warp_kernel<<<1, 32>>>(gs, K);

    int nsm = 148;
    cudaDeviceGetAttribute(&nsm, cudaDevAttrMultiProcessorCount, 0);
    int ncta = nsm * 5;

    int bands = (B + ROWS_PER_BLOCK - 1) / ROWS_PER_BLOCK;
    int total_tiles = K * bands;

    pgs_persist_kernel<<<ncta, 128>>>(x, out, D, K, B, total_tiles);
}

// round 15
// speedup vs baseline: 1.0341x; 1.0341x over previous
#include <cuda_runtime.h>
#include <cstdint>

// ---------------------------------------------------------------------------
// PrunedGroupSum: y[b,g] = (sum over contiguous column group g of x[b,:]) / 20
//   x:           [B, D] float32   (B=1024, D=262144 -> 1 GiB, streaming)
//   group_sizes: [K]    int32     (K=1000, sums to D)
//   out:         [B, K] float32
//
// R15: R12 + a third load tier. launch_bounds(128,4) lifts the reg ceiling
// to 128 so an unroll-3 main loop (24 independent LDG.128 = 12KB/warp in
// flight) runs on large groups (>=384 cols ~ 38% of bytes), falling back to
// the proven unroll-2 then single-tile tiers. The reg->in-flight->DRAM curve
// (40/80/96 regs -> 51/72/81%) is the one lever that has always paid.
// ---------------------------------------------------------------------------

#define MAX_K 4096
#define ROWS_PER_WARP 8
#define ROWS_PER_BLOCK 32

__device__ int g_offsets[MAX_K + 1];

// Single-warp scan: lane l serially sums gs[32l .. 32l+31] (int4 loads),
// shuffle-scan of the 32 lane totals gives lane bases, then lanes write the
// running prefix for their 32 elements. Requires K <= 1024 (K=1000 here).
__global__ void pgs_scan_warp_kernel(const int* __restrict__ gs, int K) {
    int lane = threadIdx.x;          // 32 threads
    int base = lane * 32;

    int v[32];
#pragma unroll
    for (int i = 0; i < 32; i += 4) {
        int idx = base + i;
        int4 t = make_int4(0, 0, 0, 0);
        if (idx + 3 < K) {
            t = *reinterpret_cast<const int4*>(gs + idx);
        } else {
            if (idx     < K) t.x = gs[idx];
            if (idx + 1 < K) t.y = gs[idx + 1];
            if (idx + 2 < K) t.z = gs[idx + 2];
            if (idx + 3 < K) t.w = gs[idx + 3];
        }
        v[i] = t.x; v[i + 1] = t.y; v[i + 2] = t.z; v[i + 3] = t.w;
    }

    int total = 0;
#pragma unroll
    for (int i = 0; i < 32; i++) total += v[i];

    // exclusive shuffle-scan of lane totals
    int run = total;
#pragma unroll
    for (int o = 1; o < 32; o <<= 1) {
        int n = __shfl_up_sync(0xffffffffu, run, o);
        if (lane >= o) run += n;
    }
    int lane_base = run - total;

    if (lane == 0) g_offsets[0] = 0;
    int acc = lane_base;
#pragma unroll
    for (int i = 0; i < 32; i++) {
        acc += v[i];
        int idx = base + i;
        if (idx < K) g_offsets[idx + 1] = acc;
    }
}

__device__ __forceinline__ float hsum4(float4 v) {
    return (v.x + v.y) + (v.z + v.w);
}

__global__ __launch_bounds__(128, 4) void pgs_sum_kernel(
    const float* __restrict__ x,
    float* __restrict__ out,
    int D, int K, int B)
{
    int g = blockIdx.x;
    int warp = threadIdx.x >> 5;
    int lane = threadIdx.x & 31;

    int row0 = blockIdx.y * ROWS_PER_BLOCK + warp * ROWS_PER_WARP;
    int nrows = B - row0;
    if (nrows <= 0) return;
    if (nrows > ROWS_PER_WARP) nrows = ROWS_PER_WARP;

    int s = g_offsets[g];
    int e = g_offsets[g + 1];

    const float* p = x + (size_t)row0 * (size_t)D;
    const size_t SD = (size_t)D;

    float acc[ROWS_PER_WARP];
#pragma unroll
    for (int r = 0; r < ROWS_PER_WARP; r++) acc[r] = 0.0f;

    int s4 = (s + 3) & ~3;
    int e4 = e & ~3;

#define LOADT(buf, col)                                                        \
    _Pragma("unroll")                                                          \
    for (int r = 0; r < ROWS_PER_WARP; r++)                                    \
        buf[r] = __ldcs(reinterpret_cast<const float4*>(p + (size_t)r * SD + (col)));

    if (nrows == ROWS_PER_WARP) {
        if (s4 >= e4) {
            // tiny group: scalar, coalesced across lanes, 8 streams
            for (int c = s + lane; c < e; c += 32) {
#pragma unroll
                for (int r = 0; r < ROWS_PER_WARP; r++)
                    acc[r] += __ldcs(p + (size_t)r * SD + c);
            }
        } else {
            // head (<=3 scalar cols)
            {
                int c = s + lane;
                if (c < s4) {
#pragma unroll
                    for (int r = 0; r < ROWS_PER_WARP; r++)
                        acc[r] += __ldcs(p + (size_t)r * SD + c);
                }
            }
            int c4 = s4 + lane * 4;
            // tier 1: unroll-3 (24 independent LDG.128 live)
            for (; c4 + 256 < e4; c4 += 384) {
                float4 v[ROWS_PER_WARP];
                float4 w[ROWS_PER_WARP];
                float4 u[ROWS_PER_WARP];
                LOADT(v, c4);
                LOADT(w, c4 + 128);
                LOADT(u, c4 + 256);
#pragma unroll
                for (int r = 0; r < ROWS_PER_WARP; r++)
                    acc[r] += (hsum4(v[r]) + hsum4(w[r])) + hsum4(u[r]);
            }
            // tier 2: unroll-2 (16 live)
            if (c4 + 128 < e4) {
                float4 v[ROWS_PER_WARP];
                float4 w[ROWS_PER_WARP];
                LOADT(v, c4);
                LOADT(w, c4 + 128);
#pragma unroll
                for (int r = 0; r < ROWS_PER_WARP; r++)
                    acc[r] += hsum4(v[r]) + hsum4(w[r]);
                c4 += 256;
            }
            // tier 3: single tile (0 or 1 per lane)
            if (c4 < e4) {
                float4 v[ROWS_PER_WARP];
                LOADT(v, c4);
#pragma unroll
                for (int r = 0; r < ROWS_PER_WARP; r++)
                    acc[r] += hsum4(v[r]);
            }
            // tail (<=3 scalar cols)
            {
                int c = e4 + lane;
                if (c < e) {
#pragma unroll
                    for (int r = 0; r < ROWS_PER_WARP; r++)
                        acc[r] += __ldcs(p + (size_t)r * SD + c);
                }
            }
        }
    } else {
        // remainder rows (B not multiple of 32): scalar per-row path
        for (int r = 0; r < nrows; r++) {
            const float* pr = p + (size_t)r * SD;
            float a = 0.f;
            for (int c = s + lane; c < e; c += 32) a += __ldcs(pr + c);
            acc[r] = a;
        }
    }

#undef LOADT

    // butterfly reduce all 8 accumulators
#pragma unroll
    for (int r = 0; r < ROWS_PER_WARP; r++) {
#pragma unroll
        for (int o = 16; o > 0; o >>= 1)
            acc[r] += __shfl_xor_sync(0xffffffffu, acc[r], o);
    }

    if (lane == 0) {
        const float inv_tau = 1.0f / 20.0f;
        size_t ob = (size_t)row0 * (size_t)K + g;
#pragma unroll
        for (int r = 0; r < ROWS_PER_WARP; r++)
            if (r < nrows) out[ob + (size_t)r * (size_t)K] = acc[r] * inv_tau;
    }
}

extern "C" void kernel_launch(void* const* d_in, const int* in_sizes, int n_in,
                              void* d_out, int out_size) {
    const float* x  = (const float*)d_in[0];
    const int*   gs = (const int*)d_in[1];

    int K = in_sizes[1];
    int B = out_size / K;
    int D = in_sizes[0] / B;

    float* out = (float*)d_out;

    pgs_scan_warp_kernel<<<1, 32>>>(gs, K);

    dim3 grid(K, (B + ROWS_PER_BLOCK - 1) / ROWS_PER_BLOCK);
    pgs_sum_kernel<<<grid, 128>>>(x, out, D, K, B);
}

// round 16
// speedup vs baseline: 1.0963x; 1.0602x over previous
#include <cuda_runtime.h>
#include <cstdint>

// ---------------------------------------------------------------------------
// PrunedGroupSum: y[b,g] = (sum over contiguous column group g of x[b,:]) / 20
//   x:           [B, D] float32   (B=1024, D=262144 -> 1 GiB, streaming)
//   group_sizes: [K]    int32     (K=1000, sums to D)
//   out:         [B, K] float32
//
// R16: R12's proven per-warp shape (8 rows/warp, unroll-2 -> 16 independent
// LDG.128, 96 regs) with one more resident warp-slot per SM: 96-thread
// blocks at launch_bounds(96,7) -> 7x3 = 21 warps/SM at the same 96-reg
// ceiling (vs R12's 5x4 = 20). Block = (group, 24 rows). In-flight bytes
// +5% at zero structural risk.
// ---------------------------------------------------------------------------

#define MAX_K 4096
#define ROWS_PER_WARP 8
#define NWARPS_BLOCK 3
#define ROWS_PER_BLOCK (NWARPS_BLOCK * ROWS_PER_WARP)   // 24

__device__ int g_offsets[MAX_K + 1];

// Single-warp scan: lane l serially sums gs[32l .. 32l+31] (int4 loads),
// shuffle-scan of the 32 lane totals gives lane bases, then lanes write the
// running prefix for their 32 elements. Requires K <= 1024 (K=1000 here).
__global__ void pgs_scan_warp_kernel(const int* __restrict__ gs, int K) {
    int lane = threadIdx.x;          // 32 threads
    int base = lane * 32;

    int v[32];
#pragma unroll
    for (int i = 0; i < 32; i += 4) {
        int idx = base + i;
        int4 t = make_int4(0, 0, 0, 0);
        if (idx + 3 < K) {
            t = *reinterpret_cast<const int4*>(gs + idx);
        } else {
            if (idx     < K) t.x = gs[idx];
            if (idx + 1 < K) t.y = gs[idx + 1];
            if (idx + 2 < K) t.z = gs[idx + 2];
            if (idx + 3 < K) t.w = gs[idx + 3];
        }
        v[i] = t.x; v[i + 1] = t.y; v[i + 2] = t.z; v[i + 3] = t.w;
    }

    int total = 0;
#pragma unroll
    for (int i = 0; i < 32; i++) total += v[i];

    // exclusive shuffle-scan of lane totals
    int run = total;
#pragma unroll
    for (int o = 1; o < 32; o <<= 1) {
        int n = __shfl_up_sync(0xffffffffu, run, o);
        if (lane >= o) run += n;
    }
    int lane_base = run - total;

    if (lane == 0) g_offsets[0] = 0;
    int acc = lane_base;
#pragma unroll
    for (int i = 0; i < 32; i++) {
        acc += v[i];
        int idx = base + i;
        if (idx < K) g_offsets[idx + 1] = acc;
    }
}

__device__ __forceinline__ float hsum4(float4 v) {
    return (v.x + v.y) + (v.z + v.w);
}

__global__ __launch_bounds__(96, 7) void pgs_sum_kernel(
    const float* __restrict__ x,
    float* __restrict__ out,
    int D, int K, int B)
{
    int g = blockIdx.x;
    int warp = threadIdx.x >> 5;
    int lane = threadIdx.x & 31;

    int row0 = blockIdx.y * ROWS_PER_BLOCK + warp * ROWS_PER_WARP;
    int nrows = B - row0;
    if (nrows <= 0) return;
    if (nrows > ROWS_PER_WARP) nrows = ROWS_PER_WARP;

    int s = g_offsets[g];
    int e = g_offsets[g + 1];

    const float* p = x + (size_t)row0 * (size_t)D;
    const size_t SD = (size_t)D;

    float acc[ROWS_PER_WARP];
#pragma unroll
    for (int r = 0; r < ROWS_PER_WARP; r++) acc[r] = 0.0f;

    int s4 = (s + 3) & ~3;
    int e4 = e & ~3;

    if (nrows == ROWS_PER_WARP) {
        if (s4 >= e4) {
            // tiny group: scalar, coalesced across lanes, 8 streams
            for (int c = s + lane; c < e; c += 32) {
#pragma unroll
                for (int r = 0; r < ROWS_PER_WARP; r++)
                    acc[r] += __ldcs(p + (size_t)r * SD + c);
            }
        } else {
            // head (<=3 scalar cols)
            {
                int c = s + lane;
                if (c < s4) {
#pragma unroll
                    for (int r = 0; r < ROWS_PER_WARP; r++)
                        acc[r] += __ldcs(p + (size_t)r * SD + c);
                }
            }
            int c4 = s4 + lane * 4;
            // unroll-2 main: 16 independent LDG.128 live at once
            for (; c4 + 128 < e4; c4 += 256) {
                float4 v[ROWS_PER_WARP];
                float4 w[ROWS_PER_WARP];
#pragma unroll
                for (int r = 0; r < ROWS_PER_WARP; r++)
                    v[r] = __ldcs(reinterpret_cast<const float4*>(p + (size_t)r * SD + c4));
#pragma unroll
                for (int r = 0; r < ROWS_PER_WARP; r++)
                    w[r] = __ldcs(reinterpret_cast<const float4*>(p + (size_t)r * SD + c4 + 128));
#pragma unroll
                for (int r = 0; r < ROWS_PER_WARP; r++)
                    acc[r] += hsum4(v[r]) + hsum4(w[r]);
            }
            // remainder vector tile (0 or 1 per lane)
            if (c4 < e4) {
                float4 v[ROWS_PER_WARP];
#pragma unroll
                for (int r = 0; r < ROWS_PER_WARP; r++)
                    v[r] = __ldcs(reinterpret_cast<const float4*>(p + (size_t)r * SD + c4));
#pragma unroll
                for (int r = 0; r < ROWS_PER_WARP; r++)
                    acc[r] += hsum4(v[r]);
            }
            // tail (<=3 scalar cols)
            {
                int c = e4 + lane;
                if (c < e) {
#pragma unroll
                    for (int r = 0; r < ROWS_PER_WARP; r++)
                        acc[r] += __ldcs(p + (size_t)r * SD + c);
                }
            }
        }
    } else {
        // remainder rows (B not multiple of 24): scalar per-row path
        for (int r = 0; r < nrows; r++) {
            const float* pr = p + (size_t)r * SD;
            float a = 0.f;
            for (int c = s + lane; c < e; c += 32) a += __ldcs(pr + c);
            acc[r] = a;
        }
    }

    // butterfly reduce all 8 accumulators
#pragma unroll
    for (int r = 0; r < ROWS_PER_WARP; r++) {
#pragma unroll
        for (int o = 16; o > 0; o >>= 1)
            acc[r] += __shfl_xor_sync(0xffffffffu, acc[r], o);
    }

    if (lane == 0) {
        const float inv_tau = 1.0f / 20.0f;
        size_t ob = (size_t)row0 * (size_t)K + g;
#pragma unroll
        for (int r = 0; r < ROWS_PER_WARP; r++)
            if (r < nrows) out[ob + (size_t)r * (size_t)K] = acc[r] * inv_tau;
    }
}

extern "C" void kernel_launch(void* const* d_in, const int* in_sizes, int n_in,
                              void* d_out, int out_size) {
    const float* x  = (const float*)d_in[0];
    const int*   gs = (const int*)d_in[1];

    int K = in_sizes[1];
    int B = out_size / K;
    int D = in_sizes[0] / B;

    float* out = (float*)d_out;

    pgs_scan_warp_kernel<<<1, 32>>>(gs, K);

    dim3 grid(K, (B + ROWS_PER_BLOCK - 1) / ROWS_PER_BLOCK);
    pgs_sum_kernel<<<grid, 96>>>(x, out, D, K, B);
}